// round 1
// baseline (speedup 1.0000x reference)
#include <cuda_runtime.h>
#include <cuda_bf16.h>
#include <math.h>

// ---------------------------------------------------------------------------
// SwinV2 window attention, fp32 baseline.
// Problem constants
// ---------------------------------------------------------------------------
#define BATCH   1024        // windows
#define NTOK    64          // tokens per window
#define DIM     512
#define HEADS   16
#define HDIM    32          // DIM / HEADS
#define NW      64          // mask batch
#define ROWS    (BATCH * NTOK)      // 65536
#define QKVCOLS (3 * DIM)           // 1536

// scratch (device globals: no alloc in kernel_launch allowed)
__device__ float g_qkv[(size_t)ROWS * QKVCOLS];       // [65536, 1536]
__device__ float g_attn_out[(size_t)ROWS * DIM];      // [65536, 512]
__device__ float g_bias_table[225 * HEADS];           // [(2*8-1)^2, 16]
__device__ float g_rel_bias[HEADS * NTOK * NTOK];     // [16, 64, 64]
__device__ float g_scale[HEADS];

// ---------------------------------------------------------------------------
// CPB MLP: hidden = relu(table @ w1^T + b1); bias_table = hidden @ w2^T
// table: [225, 2], w1: [512, 2], b1: [512], w2: [16, 512]
// ---------------------------------------------------------------------------
__global__ void cpb_mlp_kernel(const float* __restrict__ tbl,
                               const float* __restrict__ w1,
                               const float* __restrict__ b1,
                               const float* __restrict__ w2)
{
    int i = blockIdx.x;          // 0..224
    int j = threadIdx.x;         // 0..511
    __shared__ float hid[512];
    float t0 = tbl[i * 2 + 0];
    float t1 = tbl[i * 2 + 1];
    float hv = t0 * w1[j * 2 + 0] + t1 * w1[j * 2 + 1] + b1[j];
    hid[j] = fmaxf(hv, 0.0f);
    __syncthreads();

    int warp = j >> 5, lane = j & 31;   // 16 warps, warp h reduces head h
    float s = 0.0f;
    #pragma unroll
    for (int c = lane; c < 512; c += 32)
        s += hid[c] * w2[warp * 512 + c];
    #pragma unroll
    for (int off = 16; off > 0; off >>= 1)
        s += __shfl_xor_sync(0xffffffffu, s, off);
    if (lane == 0)
        g_bias_table[i * HEADS + warp] = s;
}

// expand rel_bias[h][n][m] = 16*sigmoid(bias_table[idx[n,m], h]); also scale[h]
__global__ void cpb_expand_kernel(const int* __restrict__ idx,
                                  const float* __restrict__ logit_scale)
{
    int g = blockIdx.x * 256 + threadIdx.x;   // 0..65535
    int h  = g >> 12;
    int nm = g & 4095;
    float v = g_bias_table[idx[nm] * HEADS + h];
    g_rel_bias[g] = 16.0f / (1.0f + expf(-v));
    if (g < HEADS)
        g_scale[g] = expf(fminf(logit_scale[g], 4.60517018598809136804f)); // ln(100)
}

// ---------------------------------------------------------------------------
// SGEMM (NT): C[M,N] = A[M,K] @ B[N,K]^T + bias
// BM=BN=128, BK=16, 256 threads, 8x8 per-thread tile.
// MODE 0: QKV bias (q_bias | 0 | v_bias), MODE 1: proj bias.
// M % 128 == 0, N % 128 == 0, K % 16 == 0 guaranteed by problem sizes.
// ---------------------------------------------------------------------------
template <int MODE>
__global__ __launch_bounds__(256) void sgemm_nt(
    const float* __restrict__ A, const float* __restrict__ Bm,
    const float* __restrict__ bias0, const float* __restrict__ bias1,
    float* __restrict__ C, int M, int N, int K)
{
    __shared__ float As[16][128];
    __shared__ float Bs[16][128];

    const int tid = threadIdx.x;
    const int bm = blockIdx.y * 128;
    const int bn = blockIdx.x * 128;

    const int lr = tid >> 2;            // 0..63
    const int lc = (tid & 3) * 4;       // 0,4,8,12
    const float* Ap = A + (size_t)(bm + lr) * K + lc;
    const float* Bp = Bm + (size_t)(bn + lr) * K + lc;
    const size_t rstep = (size_t)64 * K;

    const int ty = tid >> 4;            // 0..15
    const int tx = tid & 15;            // 0..15

    float acc[8][8];
    #pragma unroll
    for (int i = 0; i < 8; i++)
        #pragma unroll
        for (int j = 0; j < 8; j++) acc[i][j] = 0.0f;

    for (int k0 = 0; k0 < K; k0 += 16) {
        float4 a0 = *(const float4*)(Ap);
        float4 a1 = *(const float4*)(Ap + rstep);
        float4 b0 = *(const float4*)(Bp);
        float4 b1 = *(const float4*)(Bp + rstep);

        As[lc + 0][lr]      = a0.x; As[lc + 1][lr]      = a0.y;
        As[lc + 2][lr]      = a0.z; As[lc + 3][lr]      = a0.w;
        As[lc + 0][lr + 64] = a1.x; As[lc + 1][lr + 64] = a1.y;
        As[lc + 2][lr + 64] = a1.z; As[lc + 3][lr + 64] = a1.w;
        Bs[lc + 0][lr]      = b0.x; Bs[lc + 1][lr]      = b0.y;
        Bs[lc + 2][lr]      = b0.z; Bs[lc + 3][lr]      = b0.w;
        Bs[lc + 0][lr + 64] = b1.x; Bs[lc + 1][lr + 64] = b1.y;
        Bs[lc + 2][lr + 64] = b1.z; Bs[lc + 3][lr + 64] = b1.w;
        __syncthreads();

        #pragma unroll
        for (int kk = 0; kk < 16; kk++) {
            float4 af0 = *(const float4*)&As[kk][ty * 8];
            float4 af1 = *(const float4*)&As[kk][ty * 8 + 4];
            float4 bf0 = *(const float4*)&Bs[kk][tx * 8];
            float4 bf1 = *(const float4*)&Bs[kk][tx * 8 + 4];
            float ar[8] = {af0.x, af0.y, af0.z, af0.w, af1.x, af1.y, af1.z, af1.w};
            float br[8] = {bf0.x, bf0.y, bf0.z, bf0.w, bf1.x, bf1.y, bf1.z, bf1.w};
            #pragma unroll
            for (int i = 0; i < 8; i++)
                #pragma unroll
                for (int j = 0; j < 8; j++)
                    acc[i][j] = fmaf(ar[i], br[j], acc[i][j]);
        }
        __syncthreads();
        Ap += 16;
        Bp += 16;
    }

    // epilogue
    const int row0 = bm + ty * 8;
    const int col0 = bn + tx * 8;
    float bv[8];
    #pragma unroll
    for (int j = 0; j < 8; j++) {
        int c = col0 + j;
        if (MODE == 0) {
            bv[j] = (c < 512) ? bias0[c] : ((c < 1024) ? 0.0f : bias1[c - 1024]);
        } else {
            bv[j] = bias0[c];
        }
    }
    #pragma unroll
    for (int i = 0; i < 8; i++) {
        float* cp = C + (size_t)(row0 + i) * N + col0;
        float4 o0 = make_float4(acc[i][0] + bv[0], acc[i][1] + bv[1],
                                acc[i][2] + bv[2], acc[i][3] + bv[3]);
        float4 o1 = make_float4(acc[i][4] + bv[4], acc[i][5] + bv[5],
                                acc[i][6] + bv[6], acc[i][7] + bv[7]);
        *(float4*)(cp + 0) = o0;
        *(float4*)(cp + 4) = o1;
    }
}

// ---------------------------------------------------------------------------
// Fused window attention per (b, h):
//   S = (q·k)/(|q||k|) * scale + rel_bias[h] + mask[b%64]
//   P = softmax(S); O = P @ V  -> attn_out[(b*64+n), h*32+d]
// 256 threads per block.
// ---------------------------------------------------------------------------
__global__ __launch_bounds__(256) void attn_kernel(const float* __restrict__ qkv,
                                                   const float* __restrict__ mask,
                                                   float* __restrict__ attn_out)
{
    const int b = blockIdx.x;
    const int h = blockIdx.y;
    const int w = b & (NW - 1);
    const int tid = threadIdx.x;

    __shared__ float qs[32][64];   // [d][n]
    __shared__ float ks[32][64];   // [d][m]
    __shared__ float vs[64][32];   // [m][d]
    __shared__ float Ss[64][65];   // padded
    __shared__ float qn[64], kn[64];

    // load q,k,v (each 64x32) from qkv rows (b*64+n), cols part*512 + h*32 + d
    const float* base = qkv + (size_t)b * NTOK * QKVCOLS + h * HDIM;
    for (int e = tid; e < NTOK * HDIM; e += 256) {
        int n = e >> 5;
        int d = e & 31;
        const float* r = base + (size_t)n * QKVCOLS;
        qs[d][n] = r[d];
        ks[d][n] = r[512 + d];
        vs[n][d] = r[1024 + d];
    }
    __syncthreads();

    // inverse norms
    if (tid < 128) {
        int n = tid & 63;
        bool isq = tid < 64;
        float s = 0.0f;
        #pragma unroll
        for (int d = 0; d < 32; d++) {
            float x = isq ? qs[d][n] : ks[d][n];
            s = fmaf(x, x, s);
        }
        float inv = 1.0f / fmaxf(sqrtf(s), 1e-12f);
        if (isq) qn[n] = inv; else kn[n] = inv;
    }
    __syncthreads();

    // S = q @ k^T, 4x4 per thread
    const int ty = tid >> 4;       // 0..15 -> n block
    const int tx = tid & 15;       // 0..15 -> m block
    float acc[4][4];
    #pragma unroll
    for (int i = 0; i < 4; i++)
        #pragma unroll
        for (int j = 0; j < 4; j++) acc[i][j] = 0.0f;

    #pragma unroll
    for (int kk = 0; kk < 32; kk++) {
        float4 a = *(const float4*)&qs[kk][ty * 4];
        float4 c = *(const float4*)&ks[kk][tx * 4];
        float ar[4] = {a.x, a.y, a.z, a.w};
        float cr[4] = {c.x, c.y, c.z, c.w};
        #pragma unroll
        for (int i = 0; i < 4; i++)
            #pragma unroll
            for (int j = 0; j < 4; j++)
                acc[i][j] = fmaf(ar[i], cr[j], acc[i][j]);
    }

    const float scale = g_scale[h];
    const float* rb = g_rel_bias + h * (NTOK * NTOK);
    const float* mk = mask + (size_t)w * (NTOK * NTOK);
    #pragma unroll
    for (int i = 0; i < 4; i++) {
        int n = ty * 4 + i;
        float qi = qn[n] * scale;
        #pragma unroll
        for (int j = 0; j < 4; j++) {
            int m = tx * 4 + j;
            Ss[n][m] = acc[i][j] * qi * kn[m] + rb[n * 64 + m] + mk[n * 64 + m];
        }
    }
    __syncthreads();

    // row softmax: 8 warps x 8 rows each
    {
        int warp = tid >> 5, lane = tid & 31;
        for (int r = warp; r < 64; r += 8) {
            float x0 = Ss[r][lane];
            float x1 = Ss[r][lane + 32];
            float mx = fmaxf(x0, x1);
            #pragma unroll
            for (int off = 16; off > 0; off >>= 1)
                mx = fmaxf(mx, __shfl_xor_sync(0xffffffffu, mx, off));
            float e0 = __expf(x0 - mx);
            float e1 = __expf(x1 - mx);
            float s = e0 + e1;
            #pragma unroll
            for (int off = 16; off > 0; off >>= 1)
                s += __shfl_xor_sync(0xffffffffu, s, off);
            float inv = 1.0f / s;
            Ss[r][lane]      = e0 * inv;
            Ss[r][lane + 32] = e1 * inv;
        }
    }
    __syncthreads();

    // O = P @ V : thread -> row n = tid>>2, cols d0..d0+7
    {
        int n  = tid >> 2;
        int d0 = (tid & 3) * 8;
        float o[8];
        #pragma unroll
        for (int j = 0; j < 8; j++) o[j] = 0.0f;
        #pragma unroll
        for (int m = 0; m < 64; m++) {
            float p = Ss[n][m];
            float4 v0 = *(const float4*)&vs[m][d0];
            float4 v1 = *(const float4*)&vs[m][d0 + 4];
            o[0] = fmaf(p, v0.x, o[0]);
            o[1] = fmaf(p, v0.y, o[1]);
            o[2] = fmaf(p, v0.z, o[2]);
            o[3] = fmaf(p, v0.w, o[3]);
            o[4] = fmaf(p, v1.x, o[4]);
            o[5] = fmaf(p, v1.y, o[5]);
            o[6] = fmaf(p, v1.z, o[6]);
            o[7] = fmaf(p, v1.w, o[7]);
        }
        float* op = attn_out + ((size_t)(b * NTOK + n)) * DIM + h * HDIM + d0;
        *(float4*)(op + 0) = make_float4(o[0], o[1], o[2], o[3]);
        *(float4*)(op + 4) = make_float4(o[4], o[5], o[6], o[7]);
    }
}

// ---------------------------------------------------------------------------
// Launch
// inputs (metadata order):
//  0 x[1024,64,512] 1 mask[64,64,64] 2 qkv_w[1536,512] 3 q_bias[512]
//  4 v_bias[512] 5 logit_scale[16] 6 cpb_w1[512,2] 7 cpb_b1[512]
//  8 cpb_w2[16,512] 9 proj_w[512,512] 10 proj_b[512]
//  11 rel_coords_table[450] 12 rel_pos_index[4096] (int32)
// ---------------------------------------------------------------------------
extern "C" void kernel_launch(void* const* d_in, const int* in_sizes, int n_in,
                              void* d_out, int out_size)
{
    const float* x           = (const float*)d_in[0];
    const float* mask        = (const float*)d_in[1];
    const float* qkv_w       = (const float*)d_in[2];
    const float* q_bias      = (const float*)d_in[3];
    const float* v_bias      = (const float*)d_in[4];
    const float* logit_scale = (const float*)d_in[5];
    const float* cpb_w1      = (const float*)d_in[6];
    const float* cpb_b1      = (const float*)d_in[7];
    const float* cpb_w2      = (const float*)d_in[8];
    const float* proj_w      = (const float*)d_in[9];
    const float* proj_b      = (const float*)d_in[10];
    const float* rel_table   = (const float*)d_in[11];
    const int*   rel_idx     = (const int*)d_in[12];
    float*       out         = (float*)d_out;

    float* qkv_ptr = nullptr;
    float* attn_ptr = nullptr;
    cudaGetSymbolAddress((void**)&qkv_ptr, g_qkv);
    cudaGetSymbolAddress((void**)&attn_ptr, g_attn_out);

    // 1) CPB MLP table + bias expand + per-head scale
    cpb_mlp_kernel<<<225, 512>>>(rel_table, cpb_w1, cpb_b1, cpb_w2);
    cpb_expand_kernel<<<256, 256>>>(rel_idx, logit_scale);

    // 2) QKV GEMM: [65536,512] x [1536,512]^T -> [65536,1536]
    sgemm_nt<0><<<dim3(QKVCOLS / 128, ROWS / 128), 256>>>(
        x, qkv_w, q_bias, v_bias, qkv_ptr, ROWS, QKVCOLS, DIM);

    // 3) fused attention per (b,h)
    attn_kernel<<<dim3(BATCH, HEADS), 256>>>(qkv_ptr, mask, attn_ptr);

    // 4) output projection: [65536,512] x [512,512]^T -> d_out
    sgemm_nt<1><<<dim3(DIM / 128, ROWS / 128), 256>>>(
        attn_ptr, proj_w, proj_b, nullptr, out, ROWS, DIM, DIM);
}

// round 2
// speedup vs baseline: 1.7447x; 1.7447x over previous
#include <cuda_runtime.h>
#include <cuda_bf16.h>
#include <math.h>
#include <stdint.h>

#define BATCH   1024
#define NTOK    64
#define DIM     512
#define HEADS   16
#define HDIM    32
#define NW      64
#define ROWS    (BATCH * NTOK)      // 65536
#define QKVCOLS (3 * DIM)           // 1536

// ---------------- device scratch (no allocs allowed) ----------------
__device__ __align__(16) float         g_qkv[(size_t)ROWS * QKVCOLS];
__device__ __align__(16) __nv_bfloat16 g_xh[(size_t)ROWS * DIM];
__device__ __align__(16) __nv_bfloat16 g_xl[(size_t)ROWS * DIM];
__device__ __align__(16) __nv_bfloat16 g_wh[(size_t)QKVCOLS * DIM];
__device__ __align__(16) __nv_bfloat16 g_wl[(size_t)QKVCOLS * DIM];
__device__ __align__(16) __nv_bfloat16 g_ph[(size_t)DIM * DIM];
__device__ __align__(16) __nv_bfloat16 g_pl[(size_t)DIM * DIM];
__device__ __align__(16) __nv_bfloat16 g_aoh[(size_t)ROWS * DIM];
__device__ __align__(16) __nv_bfloat16 g_aol[(size_t)ROWS * DIM];
__device__ float g_bias_table[225 * HEADS];
__device__ float g_rel_bias[HEADS * NTOK * NTOK];
__device__ float g_scale[HEADS];

// ---------------- helpers ----------------
__device__ __forceinline__ uint32_t smem_u32(const void* p) {
    uint32_t a;
    asm("{ .reg .u64 t; cvta.to.shared.u64 t, %1; cvt.u32.u64 %0, t; }" : "=r"(a) : "l"(p));
    return a;
}

#define LDSM4(r0,r1,r2,r3, addr) \
    asm volatile("ldmatrix.sync.aligned.m8n8.x4.shared.b16 {%0,%1,%2,%3}, [%4];" \
        : "=r"(r0),"=r"(r1),"=r"(r2),"=r"(r3) : "r"(addr))

#define MMA_BF16(d, a, b) \
    asm volatile("mma.sync.aligned.m16n8k16.row.col.f32.bf16.bf16.f32 " \
        "{%0,%1,%2,%3}, {%4,%5,%6,%7}, {%8,%9}, {%0,%1,%2,%3};" \
        : "+f"(d[0]),"+f"(d[1]),"+f"(d[2]),"+f"(d[3]) \
        : "r"(a[0]),"r"(a[1]),"r"(a[2]),"r"(a[3]),"r"(b[0]),"r"(b[1]))

// ---------------- fp32 -> bf16 hi/lo split ----------------
__global__ void split_f32(const float* __restrict__ in,
                          __nv_bfloat16* __restrict__ hi,
                          __nv_bfloat16* __restrict__ lo, int n4)
{
    int i = blockIdx.x * blockDim.x + threadIdx.x;
    if (i >= n4) return;
    float4 v = ((const float4*)in)[i];
    __nv_bfloat16 h[4], l[4];
    float x[4] = {v.x, v.y, v.z, v.w};
    #pragma unroll
    for (int j = 0; j < 4; j++) {
        h[j] = __float2bfloat16(x[j]);
        l[j] = __float2bfloat16(x[j] - __bfloat162float(h[j]));
    }
    ((uint2*)hi)[i] = *(uint2*)h;
    ((uint2*)lo)[i] = *(uint2*)l;
}

// ---------------- CPB MLP ----------------
__global__ void cpb_mlp_kernel(const float* __restrict__ tbl,
                               const float* __restrict__ w1,
                               const float* __restrict__ b1,
                               const float* __restrict__ w2)
{
    int i = blockIdx.x;          // 0..224
    int j = threadIdx.x;         // 0..511
    __shared__ float hid[512];
    float hv = tbl[i*2+0] * w1[j*2+0] + tbl[i*2+1] * w1[j*2+1] + b1[j];
    hid[j] = fmaxf(hv, 0.0f);
    __syncthreads();
    int warp = j >> 5, lane = j & 31;
    float s = 0.0f;
    #pragma unroll
    for (int c = lane; c < 512; c += 32) s += hid[c] * w2[warp*512 + c];
    #pragma unroll
    for (int off = 16; off > 0; off >>= 1) s += __shfl_xor_sync(0xffffffffu, s, off);
    if (lane == 0) g_bias_table[i*HEADS + warp] = s;
}

__global__ void cpb_expand_kernel(const int* __restrict__ idx,
                                  const float* __restrict__ logit_scale)
{
    int g = blockIdx.x * 256 + threadIdx.x;
    int h = g >> 12, nm = g & 4095;
    float v = g_bias_table[idx[nm]*HEADS + h];
    g_rel_bias[g] = 16.0f / (1.0f + expf(-v));
    if (g < HEADS) g_scale[g] = expf(fminf(logit_scale[g], 4.60517018598809136804f));
}

// ---------------------------------------------------------------------------
// split-bf16 GEMM (NT): C[M,N] = (Ah+Al)[M,K] @ (Bh+Bl)[N,K]^T + bias
// BM=128 BN=64 BK=32, K=512 fixed. 256 thr = 8 warps (4m x 2n), warp 32x32.
// smem rows padded to 40 bf16 (80B) -> conflict-free ldmatrix.
// ---------------------------------------------------------------------------
template <int MODE>   // 0: qkv bias (q|0|v), 1: proj bias
__global__ __launch_bounds__(256, 2) void gemm_bf16split(
    const __nv_bfloat16* __restrict__ Ah, const __nv_bfloat16* __restrict__ Al,
    const __nv_bfloat16* __restrict__ Bh, const __nv_bfloat16* __restrict__ Bl,
    const float* __restrict__ bias0, const float* __restrict__ bias1,
    float* __restrict__ C, int N)
{
    const int K = 512;
    __shared__ __nv_bfloat16 sAh[128*40], sAl[128*40], sBh[64*40], sBl[64*40];

    const int tid  = threadIdx.x;
    const int bm   = blockIdx.y * 128;
    const int bn   = blockIdx.x * 64;
    const int wid  = tid >> 5, lane = tid & 31;
    const int wm   = (wid & 3) * 32;
    const int wn   = (wid >> 2) * 32;

    float acc[2][4][4];
    #pragma unroll
    for (int a = 0; a < 2; a++)
        #pragma unroll
        for (int b = 0; b < 4; b++)
            #pragma unroll
            for (int c = 0; c < 4; c++) acc[a][b][c] = 0.0f;

    const uint4* gAh = (const uint4*)Ah;
    const uint4* gAl = (const uint4*)Al;
    const uint4* gBh = (const uint4*)Bh;
    const uint4* gBl = (const uint4*)Bl;
    uint4* s4Ah = (uint4*)sAh;  uint4* s4Al = (uint4*)sAl;
    uint4* s4Bh = (uint4*)sBh;  uint4* s4Bl = (uint4*)sBl;

    // ldmatrix smem addresses (constant across k-loop except k offset)
    const uint32_t aAh = smem_u32(sAh), aAl = smem_u32(sAl);
    const uint32_t aBh = smem_u32(sBh), aBl = smem_u32(sBl);

    for (int k0 = 0; k0 < K; k0 += 32) {
        // ---- load tiles (chunks of 8 bf16 = 16B) ----
        {
            int c0 = tid, c1 = tid + 256;
            int r0 = c0 >> 2, q0 = c0 & 3;
            int r1 = c1 >> 2, q1 = c1 & 3;
            size_t gi0 = (size_t)(bm + r0) * 64 + (k0 >> 3) + q0;
            size_t gi1 = (size_t)(bm + r1) * 64 + (k0 >> 3) + q1;
            s4Ah[r0*5 + q0] = gAh[gi0];
            s4Ah[r1*5 + q1] = gAh[gi1];
            s4Al[r0*5 + q0] = gAl[gi0];
            s4Al[r1*5 + q1] = gAl[gi1];
            size_t gb = (size_t)(bn + r0) * 64 + (k0 >> 3) + q0;   // r0 in 0..63
            s4Bh[r0*5 + q0] = gBh[gb];
            s4Bl[r0*5 + q0] = gBl[gb];
        }
        __syncthreads();

        #pragma unroll
        for (int ks = 0; ks < 2; ks++) {
            const int kb = ks * 16;
            uint32_t ah[2][4], al[2][4], bh[4][2], bl[4][2];
            #pragma unroll
            for (int mt = 0; mt < 2; mt++) {
                int row = wm + mt*16 + (lane & 15);
                int col = kb + (lane >> 4) * 8;
                uint32_t off = (uint32_t)(row*40 + col) * 2;
                LDSM4(ah[mt][0], ah[mt][1], ah[mt][2], ah[mt][3], aAh + off);
                LDSM4(al[mt][0], al[mt][1], al[mt][2], al[mt][3], aAl + off);
            }
            #pragma unroll
            for (int np = 0; np < 2; np++) {
                int g = lane >> 3;
                int row = wn + np*16 + (lane & 7) + ((g >> 1) & 1) * 8;
                int col = kb + (g & 1) * 8;
                uint32_t off = (uint32_t)(row*40 + col) * 2;
                LDSM4(bh[2*np][0], bh[2*np][1], bh[2*np+1][0], bh[2*np+1][1], aBh + off);
                LDSM4(bl[2*np][0], bl[2*np][1], bl[2*np+1][0], bl[2*np+1][1], aBl + off);
            }
            #pragma unroll
            for (int mt = 0; mt < 2; mt++)
                #pragma unroll
                for (int nt = 0; nt < 4; nt++) {
                    MMA_BF16(acc[mt][nt], ah[mt], bh[nt]);
                    MMA_BF16(acc[mt][nt], ah[mt], bl[nt]);
                    MMA_BF16(acc[mt][nt], al[mt], bh[nt]);
                }
        }
        __syncthreads();
    }

    // ---- epilogue ----
    #pragma unroll
    for (int mt = 0; mt < 2; mt++) {
        #pragma unroll
        for (int nt = 0; nt < 4; nt++) {
            int row = bm + wm + mt*16 + (lane >> 2);
            int col = bn + wn + nt*8 + (lane & 3)*2;
            float b0, b1;
            if (MODE == 0) {
                b0 = (col   < 512) ? bias0[col]   : ((col   < 1024) ? 0.0f : bias1[col - 1024]);
                b1 = (col+1 < 512) ? bias0[col+1] : ((col+1 < 1024) ? 0.0f : bias1[col+1 - 1024]);
            } else {
                b0 = bias0[col]; b1 = bias0[col+1];
            }
            float* p0 = C + (size_t)row * N + col;
            float* p1 = C + (size_t)(row + 8) * N + col;
            p0[0] = acc[mt][nt][0] + b0;  p0[1] = acc[mt][nt][1] + b1;
            p1[0] = acc[mt][nt][2] + b0;  p1[1] = acc[mt][nt][3] + b1;
        }
    }
}

// ---------------------------------------------------------------------------
// Fused window attention per (b,h). Register-resident S + warp softmax.
// Writes attn output directly as bf16 hi/lo for the proj GEMM.
// ---------------------------------------------------------------------------
__global__ __launch_bounds__(256) void attn_kernel(const float* __restrict__ qkv,
                                                   const float* __restrict__ mask,
                                                   __nv_bfloat16* __restrict__ aoh,
                                                   __nv_bfloat16* __restrict__ aol)
{
    const int b = blockIdx.x;
    const int h = blockIdx.y;
    const int w = b & (NW - 1);
    const int tid = threadIdx.x;
    const int wid = tid >> 5, lane = tid & 31;

    __shared__ float qs[32][64];     // [d][n]
    __shared__ float ks[32][64];     // [d][m]
    __shared__ float vs[64][32];     // [m][d]
    __shared__ float Pt[64][68];     // P transposed [m][n], pad 68 (16B-aligned rows)
    __shared__ float qn[64], kn[64];

    const float* base = qkv + (size_t)b * NTOK * QKVCOLS + h * HDIM;
    for (int e = tid; e < NTOK * HDIM; e += 256) {
        int n = e >> 5, d = e & 31;
        const float* r = base + (size_t)n * QKVCOLS;
        qs[d][n] = r[d];
        ks[d][n] = r[512 + d];
        vs[n][d] = r[1024 + d];
    }
    __syncthreads();

    if (tid < 128) {
        int n = tid & 63;
        bool isq = tid < 64;
        float s = 0.0f;
        #pragma unroll
        for (int d = 0; d < 32; d++) {
            float x = isq ? qs[d][n] : ks[d][n];
            s = fmaf(x, x, s);
        }
        float inv = 1.0f / fmaxf(sqrtf(s), 1e-12f);
        if (isq) qn[n] = inv; else kn[n] = inv;
    }
    __syncthreads();

    // ---- S: warp wid owns rows n = wid*8 .. wid*8+7; lane owns cols m=lane, lane+32
    float s0[8], s1[8];
    #pragma unroll
    for (int r = 0; r < 8; r++) { s0[r] = 0.0f; s1[r] = 0.0f; }
    #pragma unroll
    for (int d = 0; d < 32; d++) {
        float kv0 = ks[d][lane];
        float kv1 = ks[d][lane + 32];
        #pragma unroll
        for (int r = 0; r < 8; r++) {
            float qv = qs[d][wid*8 + r];        // broadcast
            s0[r] = fmaf(qv, kv0, s0[r]);
            s1[r] = fmaf(qv, kv1, s1[r]);
        }
    }

    const float scale = g_scale[h];
    const float kn0 = kn[lane], kn1 = kn[lane + 32];
    const float* rb = g_rel_bias + h * (NTOK * NTOK);
    const float* mk = mask + (size_t)w * (NTOK * NTOK);

    #pragma unroll
    for (int r = 0; r < 8; r++) {
        int n = wid*8 + r;
        float qsc = qn[n] * scale;
        int off = n*64 + lane;
        float x0 = s0[r]*qsc*kn0 + rb[off]      + mk[off];
        float x1 = s1[r]*qsc*kn1 + rb[off + 32] + mk[off + 32];
        float mx = fmaxf(x0, x1);
        #pragma unroll
        for (int o = 16; o > 0; o >>= 1)
            mx = fmaxf(mx, __shfl_xor_sync(0xffffffffu, mx, o));
        float e0 = __expf(x0 - mx);
        float e1 = __expf(x1 - mx);
        float sm = e0 + e1;
        #pragma unroll
        for (int o = 16; o > 0; o >>= 1)
            sm += __shfl_xor_sync(0xffffffffu, sm, o);
        float inv = 1.0f / sm;
        Pt[lane][n]      = e0 * inv;
        Pt[lane + 32][n] = e1 * inv;
    }
    __syncthreads();

    // ---- PV: warp wid owns rows n = wid*8..+7; lane owns col d = lane
    float o[8];
    #pragma unroll
    for (int r = 0; r < 8; r++) o[r] = 0.0f;
    #pragma unroll
    for (int m = 0; m < 64; m++) {
        float vm = vs[m][lane];
        float4 p0 = *(const float4*)&Pt[m][wid*8];      // broadcast 128b
        float4 p1 = *(const float4*)&Pt[m][wid*8 + 4];
        o[0] = fmaf(p0.x, vm, o[0]);  o[1] = fmaf(p0.y, vm, o[1]);
        o[2] = fmaf(p0.z, vm, o[2]);  o[3] = fmaf(p0.w, vm, o[3]);
        o[4] = fmaf(p1.x, vm, o[4]);  o[5] = fmaf(p1.y, vm, o[5]);
        o[6] = fmaf(p1.z, vm, o[6]);  o[7] = fmaf(p1.w, vm, o[7]);
    }
    #pragma unroll
    for (int r = 0; r < 8; r++) {
        size_t oi = (size_t)(b*NTOK + wid*8 + r) * DIM + h*HDIM + lane;
        __nv_bfloat16 hi = __float2bfloat16(o[r]);
        __nv_bfloat16 lo = __float2bfloat16(o[r] - __bfloat162float(hi));
        aoh[oi] = hi;
        aol[oi] = lo;
    }
}

// ---------------------------------------------------------------------------
extern "C" void kernel_launch(void* const* d_in, const int* in_sizes, int n_in,
                              void* d_out, int out_size)
{
    const float* x           = (const float*)d_in[0];
    const float* mask        = (const float*)d_in[1];
    const float* qkv_w       = (const float*)d_in[2];
    const float* q_bias      = (const float*)d_in[3];
    const float* v_bias      = (const float*)d_in[4];
    const float* logit_scale = (const float*)d_in[5];
    const float* cpb_w1      = (const float*)d_in[6];
    const float* cpb_b1      = (const float*)d_in[7];
    const float* cpb_w2      = (const float*)d_in[8];
    const float* proj_w      = (const float*)d_in[9];
    const float* proj_b      = (const float*)d_in[10];
    const float* rel_table   = (const float*)d_in[11];
    const int*   rel_idx     = (const int*)d_in[12];
    float*       out         = (float*)d_out;

    float *qkv_ptr;
    __nv_bfloat16 *xh, *xl, *wh, *wl, *ph, *pl, *aoh, *aol;
    cudaGetSymbolAddress((void**)&qkv_ptr, g_qkv);
    cudaGetSymbolAddress((void**)&xh, g_xh);   cudaGetSymbolAddress((void**)&xl, g_xl);
    cudaGetSymbolAddress((void**)&wh, g_wh);   cudaGetSymbolAddress((void**)&wl, g_wl);
    cudaGetSymbolAddress((void**)&ph, g_ph);   cudaGetSymbolAddress((void**)&pl, g_pl);
    cudaGetSymbolAddress((void**)&aoh, g_aoh); cudaGetSymbolAddress((void**)&aol, g_aol);

    // splits
    {
        int n4 = ROWS * DIM / 4;
        split_f32<<<(n4 + 255)/256, 256>>>(x, xh, xl, n4);
        n4 = QKVCOLS * DIM / 4;
        split_f32<<<(n4 + 255)/256, 256>>>(qkv_w, wh, wl, n4);
        n4 = DIM * DIM / 4;
        split_f32<<<(n4 + 255)/256, 256>>>(proj_w, ph, pl, n4);
    }

    // CPB
    cpb_mlp_kernel<<<225, 512>>>(rel_table, cpb_w1, cpb_b1, cpb_w2);
    cpb_expand_kernel<<<256, 256>>>(rel_idx, logit_scale);

    // QKV GEMM: [65536,512] x [1536,512]^T -> fp32 [65536,1536]
    gemm_bf16split<0><<<dim3(QKVCOLS/64, ROWS/128), 256>>>(
        xh, xl, wh, wl, q_bias, v_bias, qkv_ptr, QKVCOLS);

    // attention (writes bf16 hi/lo)
    attn_kernel<<<dim3(BATCH, HEADS), 256>>>(qkv_ptr, mask, aoh, aol);

    // proj GEMM: [65536,512] x [512,512]^T -> d_out fp32
    gemm_bf16split<1><<<dim3(DIM/64, ROWS/128), 256>>>(
        aoh, aol, ph, pl, proj_b, nullptr, out, DIM);
}

// round 4
// speedup vs baseline: 1.8968x; 1.0872x over previous
#include <cuda_runtime.h>
#include <cuda_bf16.h>
#include <math.h>
#include <stdint.h>

#define BATCH   1024
#define NTOK    64
#define DIM     512
#define HEADS   16
#define HDIM    32
#define NW      64
#define ROWS    (BATCH * NTOK)      // 65536
#define QKVCOLS (3 * DIM)           // 1536

// ---------------- device scratch ----------------
__device__ __align__(16) float         g_qkv[(size_t)ROWS * QKVCOLS];
__device__ __align__(16) __nv_bfloat16 g_xh[(size_t)ROWS * DIM];
__device__ __align__(16) __nv_bfloat16 g_xl[(size_t)ROWS * DIM];
__device__ __align__(16) __nv_bfloat16 g_wh[(size_t)QKVCOLS * DIM];
__device__ __align__(16) __nv_bfloat16 g_wl[(size_t)QKVCOLS * DIM];
__device__ __align__(16) __nv_bfloat16 g_ph[(size_t)DIM * DIM];
__device__ __align__(16) __nv_bfloat16 g_pl[(size_t)DIM * DIM];
__device__ __align__(16) __nv_bfloat16 g_aoh[(size_t)ROWS * DIM];
__device__ __align__(16) __nv_bfloat16 g_aol[(size_t)ROWS * DIM];
__device__ float g_bias_table[225 * HEADS];
__device__ float g_rel_bias[HEADS * NTOK * NTOK];
__device__ float g_scale[HEADS];

// ---------------- helpers ----------------
__device__ __forceinline__ uint32_t smem_u32(const void* p) {
    uint32_t a;
    asm("{ .reg .u64 t; cvta.to.shared.u64 t, %1; cvt.u32.u64 %0, t; }" : "=r"(a) : "l"(p));
    return a;
}

#define LDSM4(r0,r1,r2,r3, addr) \
    asm volatile("ldmatrix.sync.aligned.m8n8.x4.shared.b16 {%0,%1,%2,%3}, [%4];" \
        : "=r"(r0),"=r"(r1),"=r"(r2),"=r"(r3) : "r"(addr))

#define MMA_BF16(d, a, b) \
    asm volatile("mma.sync.aligned.m16n8k16.row.col.f32.bf16.bf16.f32 " \
        "{%0,%1,%2,%3}, {%4,%5,%6,%7}, {%8,%9}, {%0,%1,%2,%3};" \
        : "+f"(d[0]),"+f"(d[1]),"+f"(d[2]),"+f"(d[3]) \
        : "r"(a[0]),"r"(a[1]),"r"(a[2]),"r"(a[3]),"r"(b[0]),"r"(b[1]))

#define CP16(dst, src) \
    asm volatile("cp.async.ca.shared.global [%0], [%1], 16;" :: "r"(dst), "l"(src))
#define CP_COMMIT() asm volatile("cp.async.commit_group;" ::: "memory")
#define CP_WAIT1()  asm volatile("cp.async.wait_group 1;" ::: "memory")

// ---------------- fp32 -> bf16 hi/lo split ----------------
__global__ void split_f32(const float* __restrict__ in,
                          __nv_bfloat16* __restrict__ hi,
                          __nv_bfloat16* __restrict__ lo, int n4)
{
    int i = blockIdx.x * blockDim.x + threadIdx.x;
    if (i >= n4) return;
    float4 v = ((const float4*)in)[i];
    __nv_bfloat16 h[4], l[4];
    float x[4] = {v.x, v.y, v.z, v.w};
    #pragma unroll
    for (int j = 0; j < 4; j++) {
        h[j] = __float2bfloat16(x[j]);
        l[j] = __float2bfloat16(x[j] - __bfloat162float(h[j]));
    }
    ((uint2*)hi)[i] = *(uint2*)h;
    ((uint2*)lo)[i] = *(uint2*)l;
}

// ---------------- CPB MLP ----------------
__global__ void cpb_mlp_kernel(const float* __restrict__ tbl,
                               const float* __restrict__ w1,
                               const float* __restrict__ b1,
                               const float* __restrict__ w2)
{
    int i = blockIdx.x, j = threadIdx.x;
    __shared__ float hid[512];
    float hv = tbl[i*2+0] * w1[j*2+0] + tbl[i*2+1] * w1[j*2+1] + b1[j];
    hid[j] = fmaxf(hv, 0.0f);
    __syncthreads();
    int warp = j >> 5, lane = j & 31;
    float s = 0.0f;
    #pragma unroll
    for (int c = lane; c < 512; c += 32) s += hid[c] * w2[warp*512 + c];
    #pragma unroll
    for (int off = 16; off > 0; off >>= 1) s += __shfl_xor_sync(0xffffffffu, s, off);
    if (lane == 0) g_bias_table[i*HEADS + warp] = s;
}

__global__ void cpb_expand_kernel(const int* __restrict__ idx,
                                  const float* __restrict__ logit_scale)
{
    int g = blockIdx.x * 256 + threadIdx.x;
    int h = g >> 12, nm = g & 4095;
    float v = g_bias_table[idx[nm]*HEADS + h];
    g_rel_bias[g] = 16.0f / (1.0f + expf(-v));
    if (g < HEADS) g_scale[g] = expf(fminf(logit_scale[g], 4.60517018598809136804f));
}

// ---------------------------------------------------------------------------
// split-bf16 GEMM (NT): C[M,N] = (Ah+Al)[M,K] @ (Bh+Bl)[N,K]^T + bias
// BM=128 BN=64 BK=32, K=512. 256 thr = 8 warps (4m x 2n), warp 32x32.
// 3-stage cp.async pipeline. smem rows padded to 40 bf16 (conflict-free LDSM).
// stage layout (bytes): [Ah 10240 | Al 10240 | Bh 5120 | Bl 5120] = 30720
// ---------------------------------------------------------------------------
#define A_BYTES 10240
#define B_BYTES 5120
#define STG_BYTES (2*A_BYTES + 2*B_BYTES)   // 30720
#define GEMM_SMEM (3 * STG_BYTES)           // 92160

template <int MODE>   // 0: qkv bias (q|0|v), 1: proj bias
__global__ __launch_bounds__(256, 2) void gemm_bf16split(
    const __nv_bfloat16* __restrict__ Ah, const __nv_bfloat16* __restrict__ Al,
    const __nv_bfloat16* __restrict__ Bh, const __nv_bfloat16* __restrict__ Bl,
    const float* __restrict__ bias0, const float* __restrict__ bias1,
    float* __restrict__ C, int N)
{
    extern __shared__ char smem[];

    const int tid  = threadIdx.x;
    const int bm   = blockIdx.y * 128;
    const int bn   = blockIdx.x * 64;
    const int wid  = tid >> 5, lane = tid & 31;
    const int wm   = (wid & 3) * 32;
    const int wn   = (wid >> 2) * 32;

    const uint32_t sbase = smem_u32(smem);

    float acc[2][4][4];
    #pragma unroll
    for (int a = 0; a < 2; a++)
        #pragma unroll
        for (int b = 0; b < 4; b++)
            #pragma unroll
            for (int c = 0; c < 4; c++) acc[a][b][c] = 0.0f;

    // --- stage loader: BK=32 cols = 4 x 16B chunks per row ---
    const int lrow = tid >> 2;       // 0..63
    const int lq   = tid & 3;        // 0..3
    auto load_stage = [&](int kt, int buf) {
        const uint32_t sb = sbase + buf * STG_BYTES;
        const int k0 = kt * 32;
        // A: 128 rows x 4 chunks, hi+lo (2 iters of 64 rows)
        #pragma unroll
        for (int i = 0; i < 2; i++) {
            int row = lrow + i * 64;
            uint32_t d = sb + (uint32_t)(row * 80 + lq * 16);
            const char* sh = (const char*)Ah + ((size_t)(bm + row) * 512 + k0 + lq * 8) * 2;
            const char* sl = (const char*)Al + ((size_t)(bm + row) * 512 + k0 + lq * 8) * 2;
            CP16(d, sh);
            CP16(d + A_BYTES, sl);
        }
        // B: 64 rows x 4 chunks, hi+lo
        {
            uint32_t d = sb + 2*A_BYTES + (uint32_t)(lrow * 80 + lq * 16);
            const char* sh = (const char*)Bh + ((size_t)(bn + lrow) * 512 + k0 + lq * 8) * 2;
            const char* sl = (const char*)Bl + ((size_t)(bn + lrow) * 512 + k0 + lq * 8) * 2;
            CP16(d, sh);
            CP16(d + B_BYTES, sl);
        }
        CP_COMMIT();
    };

    load_stage(0, 0);
    load_stage(1, 1);

    for (int kt = 0; kt < 16; kt++) {
        const int buf = kt % 3;
        CP_WAIT1();
        __syncthreads();

        if (kt + 2 < 16) load_stage(kt + 2, (kt + 2) % 3);
        else CP_COMMIT();   // keep group accounting uniform

        const uint32_t sb  = sbase + buf * STG_BYTES;
        const uint32_t aAh = sb;
        const uint32_t aAl = sb + A_BYTES;
        const uint32_t aBh = sb + 2*A_BYTES;
        const uint32_t aBl = sb + 2*A_BYTES + B_BYTES;

        #pragma unroll
        for (int ks = 0; ks < 2; ks++) {
            const int kb = ks * 16;
            uint32_t ah[2][4], al[2][4], bh[4][2], bl[4][2];
            #pragma unroll
            for (int mt = 0; mt < 2; mt++) {
                int row = wm + mt*16 + (lane & 15);
                int col = kb + (lane >> 4) * 8;
                uint32_t off = (uint32_t)(row*40 + col) * 2;
                LDSM4(ah[mt][0], ah[mt][1], ah[mt][2], ah[mt][3], aAh + off);
                LDSM4(al[mt][0], al[mt][1], al[mt][2], al[mt][3], aAl + off);
            }
            #pragma unroll
            for (int np = 0; np < 2; np++) {
                int g = lane >> 3;
                int row = wn + np*16 + (lane & 7) + ((g >> 1) & 1) * 8;
                int col = kb + (g & 1) * 8;
                uint32_t off = (uint32_t)(row*40 + col) * 2;
                LDSM4(bh[2*np][0], bh[2*np][1], bh[2*np+1][0], bh[2*np+1][1], aBh + off);
                LDSM4(bl[2*np][0], bl[2*np][1], bl[2*np+1][0], bl[2*np+1][1], aBl + off);
            }
            #pragma unroll
            for (int mt = 0; mt < 2; mt++)
                #pragma unroll
                for (int nt = 0; nt < 4; nt++) {
                    MMA_BF16(acc[mt][nt], ah[mt], bh[nt]);
                    MMA_BF16(acc[mt][nt], ah[mt], bl[nt]);
                    MMA_BF16(acc[mt][nt], al[mt], bh[nt]);
                }
        }
        __syncthreads();
    }

    // ---- epilogue ----
    #pragma unroll
    for (int mt = 0; mt < 2; mt++) {
        #pragma unroll
        for (int nt = 0; nt < 4; nt++) {
            int row = bm + wm + mt*16 + (lane >> 2);
            int col = bn + wn + nt*8 + (lane & 3)*2;
            float b0, b1;
            if (MODE == 0) {
                b0 = (col   < 512) ? bias0[col]   : ((col   < 1024) ? 0.0f : bias1[col - 1024]);
                b1 = (col+1 < 512) ? bias0[col+1] : ((col+1 < 1024) ? 0.0f : bias1[col+1 - 1024]);
            } else {
                b0 = bias0[col]; b1 = bias0[col+1];
            }
            float* p0 = C + (size_t)row * N + col;
            float* p1 = C + (size_t)(row + 8) * N + col;
            p0[0] = acc[mt][nt][0] + b0;  p0[1] = acc[mt][nt][1] + b1;
            p1[0] = acc[mt][nt][2] + b0;  p1[1] = acc[mt][nt][3] + b1;
        }
    }
}

// ---------------------------------------------------------------------------
// Fused window attention per (b,h). Register-resident S + warp softmax.
// Writes attn output directly as bf16 hi/lo for the proj GEMM.
// ---------------------------------------------------------------------------
__global__ __launch_bounds__(256) void attn_kernel(const float* __restrict__ qkv,
                                                   const float* __restrict__ mask,
                                                   __nv_bfloat16* __restrict__ aoh,
                                                   __nv_bfloat16* __restrict__ aol)
{
    const int b = blockIdx.x;
    const int h = blockIdx.y;
    const int w = b & (NW - 1);
    const int tid = threadIdx.x;
    const int wid = tid >> 5, lane = tid & 31;

    __shared__ float qs[32][64];
    __shared__ float ks[32][64];
    __shared__ float vs[64][32];
    __shared__ float Pt[64][68];
    __shared__ float qn[64], kn[64];

    const float* base = qkv + (size_t)b * NTOK * QKVCOLS + h * HDIM;
    for (int e = tid; e < NTOK * HDIM; e += 256) {
        int n = e >> 5, d = e & 31;
        const float* r = base + (size_t)n * QKVCOLS;
        qs[d][n] = r[d];
        ks[d][n] = r[512 + d];
        vs[n][d] = r[1024 + d];
    }
    __syncthreads();

    if (tid < 128) {
        int n = tid & 63;
        bool isq = tid < 64;
        float s = 0.0f;
        #pragma unroll
        for (int d = 0; d < 32; d++) {
            float x = isq ? qs[d][n] : ks[d][n];
            s = fmaf(x, x, s);
        }
        float inv = 1.0f / fmaxf(sqrtf(s), 1e-12f);
        if (isq) qn[n] = inv; else kn[n] = inv;
    }
    __syncthreads();

    float s0[8], s1[8];
    #pragma unroll
    for (int r = 0; r < 8; r++) { s0[r] = 0.0f; s1[r] = 0.0f; }
    #pragma unroll
    for (int d = 0; d < 32; d++) {
        float kv0 = ks[d][lane];
        float kv1 = ks[d][lane + 32];
        #pragma unroll
        for (int r = 0; r < 8; r++) {
            float qv = qs[d][wid*8 + r];
            s0[r] = fmaf(qv, kv0, s0[r]);
            s1[r] = fmaf(qv, kv1, s1[r]);
        }
    }

    const float scale = g_scale[h];
    const float kn0 = kn[lane], kn1 = kn[lane + 32];
    const float* rb = g_rel_bias + h * (NTOK * NTOK);
    const float* mk = mask + (size_t)w * (NTOK * NTOK);

    #pragma unroll
    for (int r = 0; r < 8; r++) {
        int n = wid*8 + r;
        float qsc = qn[n] * scale;
        int off = n*64 + lane;
        float x0 = s0[r]*qsc*kn0 + rb[off]      + mk[off];
        float x1 = s1[r]*qsc*kn1 + rb[off + 32] + mk[off + 32];
        float mx = fmaxf(x0, x1);
        #pragma unroll
        for (int o = 16; o > 0; o >>= 1)
            mx = fmaxf(mx, __shfl_xor_sync(0xffffffffu, mx, o));
        float e0 = __expf(x0 - mx);
        float e1 = __expf(x1 - mx);
        float sm = e0 + e1;
        #pragma unroll
        for (int o = 16; o > 0; o >>= 1)
            sm += __shfl_xor_sync(0xffffffffu, sm, o);
        float inv = 1.0f / sm;
        Pt[lane][n]      = e0 * inv;
        Pt[lane + 32][n] = e1 * inv;
    }
    __syncthreads();

    float o[8];
    #pragma unroll
    for (int r = 0; r < 8; r++) o[r] = 0.0f;
    #pragma unroll
    for (int m = 0; m < 64; m++) {
        float vm = vs[m][lane];
        float4 p0 = *(const float4*)&Pt[m][wid*8];
        float4 p1 = *(const float4*)&Pt[m][wid*8 + 4];
        o[0] = fmaf(p0.x, vm, o[0]);  o[1] = fmaf(p0.y, vm, o[1]);
        o[2] = fmaf(p0.z, vm, o[2]);  o[3] = fmaf(p0.w, vm, o[3]);
        o[4] = fmaf(p1.x, vm, o[4]);  o[5] = fmaf(p1.y, vm, o[5]);
        o[6] = fmaf(p1.z, vm, o[6]);  o[7] = fmaf(p1.w, vm, o[7]);
    }
    #pragma unroll
    for (int r = 0; r < 8; r++) {
        size_t oi = (size_t)(b*NTOK + wid*8 + r) * DIM + h*HDIM + lane;
        __nv_bfloat16 hi = __float2bfloat16(o[r]);
        __nv_bfloat16 lo = __float2bfloat16(o[r] - __bfloat162float(hi));
        aoh[oi] = hi;
        aol[oi] = lo;
    }
}

// ---------------------------------------------------------------------------
extern "C" void kernel_launch(void* const* d_in, const int* in_sizes, int n_in,
                              void* d_out, int out_size)
{
    const float* x           = (const float*)d_in[0];
    const float* mask        = (const float*)d_in[1];
    const float* qkv_w       = (const float*)d_in[2];
    const float* q_bias      = (const float*)d_in[3];
    const float* v_bias      = (const float*)d_in[4];
    const float* logit_scale = (const float*)d_in[5];
    const float* cpb_w1      = (const float*)d_in[6];
    const float* cpb_b1      = (const float*)d_in[7];
    const float* cpb_w2      = (const float*)d_in[8];
    const float* proj_w      = (const float*)d_in[9];
    const float* proj_b      = (const float*)d_in[10];
    const float* rel_table   = (const float*)d_in[11];
    const int*   rel_idx     = (const int*)d_in[12];
    float*       out         = (float*)d_out;

    float *qkv_ptr;
    __nv_bfloat16 *xh, *xl, *wh, *wl, *ph, *pl, *aoh, *aol;
    cudaGetSymbolAddress((void**)&qkv_ptr, g_qkv);
    cudaGetSymbolAddress((void**)&xh, g_xh);   cudaGetSymbolAddress((void**)&xl, g_xl);
    cudaGetSymbolAddress((void**)&wh, g_wh);   cudaGetSymbolAddress((void**)&wl, g_wl);
    cudaGetSymbolAddress((void**)&ph, g_ph);   cudaGetSymbolAddress((void**)&pl, g_pl);
    cudaGetSymbolAddress((void**)&aoh, g_aoh); cudaGetSymbolAddress((void**)&aol, g_aol);

    cudaFuncSetAttribute(gemm_bf16split<0>, cudaFuncAttributeMaxDynamicSharedMemorySize, GEMM_SMEM);
    cudaFuncSetAttribute(gemm_bf16split<1>, cudaFuncAttributeMaxDynamicSharedMemorySize, GEMM_SMEM);

    // splits
    {
        int n4 = ROWS * DIM / 4;
        split_f32<<<(n4 + 255)/256, 256>>>(x, xh, xl, n4);
        n4 = QKVCOLS * DIM / 4;
        split_f32<<<(n4 + 255)/256, 256>>>(qkv_w, wh, wl, n4);
        n4 = DIM * DIM / 4;
        split_f32<<<(n4 + 255)/256, 256>>>(proj_w, ph, pl, n4);
    }

    // CPB
    cpb_mlp_kernel<<<225, 512>>>(rel_table, cpb_w1, cpb_b1, cpb_w2);
    cpb_expand_kernel<<<256, 256>>>(rel_idx, logit_scale);

    // QKV GEMM: [65536,512] x [1536,512]^T -> fp32 [65536,1536]
    gemm_bf16split<0><<<dim3(QKVCOLS/64, ROWS/128), 256, GEMM_SMEM>>>(
        xh, xl, wh, wl, q_bias, v_bias, qkv_ptr, QKVCOLS);

    // attention (writes bf16 hi/lo)
    attn_kernel<<<dim3(BATCH, HEADS), 256>>>(qkv_ptr, mask, aoh, aol);

    // proj GEMM: [65536,512] x [512,512]^T -> d_out fp32
    gemm_bf16split<1><<<dim3(DIM/64, ROWS/128), 256, GEMM_SMEM>>>(
        aoh, aol, ph, pl, proj_b, nullptr, out, DIM);
}